// round 10
// baseline (speedup 1.0000x reference)
#include <cuda_runtime.h>
#include <math_constants.h>
#include <mma.h>

using namespace nvcuda;

// Problem shape (fixed by the dataset)
#define NB 4
#define NQ 2048
#define NR 16384
#define DIM 64
#define KK 16
#define KC 20                   // candidates kept per split (margin over KK)
#define NSPLIT 4
#define QPB 128                 // queries per block
#define TRR 64                  // refs per tile
#define RPS (NR / NSPLIT)       // 4096 refs per split
#define NTILE (RPS / TRR)       // 64 tiles per split
#define NCAND (NSPLIT * KC)     // 80 candidates per query

// Dynamic smem layout (floats):
//   s_q     [QPB*DIM]      = 8192   (-2 * query tile, row-major lda=64)
//   s_ref   [2][TRR*DIM]   = 8192   (ref rows; used as B col-major ldb=64)
//   s_r2t   [2][TRR]       = 128
//   s_score [TRR*QPB]      = 8192   (col-major acc store: score[r*128+q])
//   s_val   [KC*QPB]       = 2560
//   s_idx   [KC*QPB] u16   = 1280 floats-worth (2560 bytes)
#define OFF_Q     0
#define OFF_REF   (OFF_Q + QPB * DIM)
#define OFF_R2T   (OFF_REF + 2 * TRR * DIM)
#define OFF_SCORE (OFF_R2T + 2 * TRR)
#define OFF_VAL   (OFF_SCORE + TRR * QPB)
#define OFF_IDX   (OFF_VAL + KC * QPB)
#define SMEM_FLOATS (OFF_IDX + (KC * QPB) / 2)
#define SMEM_BYTES (SMEM_FLOATS * 4)

// Scratch (device globals: harness forbids cudaMalloc)
__device__ float g_r2[NB * NR];
__device__ int   g_cand[(size_t)NB * NQ * NCAND];

// cp.async helpers
__device__ __forceinline__ void cp16(unsigned int dst, const void* src) {
    asm volatile("cp.async.cg.shared.global [%0], [%1], 16;" :: "r"(dst), "l"(src));
}
__device__ __forceinline__ void cp4(unsigned int dst, const void* src) {
    asm volatile("cp.async.ca.shared.global [%0], [%1], 4;" :: "r"(dst), "l"(src));
}
__device__ __forceinline__ void cp_commit() { asm volatile("cp.async.commit_group;"); }
__device__ __forceinline__ void cp_wait0()  { asm volatile("cp.async.wait_group 0;" ::: "memory"); }

// ---------------------------------------------------------------------------
// XLA-GPU row-reduction emulation for sum(x*x) over 64 elements (verified
// bit-exact vs reference in R8): strided lane accum + shfl_down tree.
// ---------------------------------------------------------------------------
__device__ __forceinline__ float xla_row_sumsq(const float* __restrict__ x) {
    float a[32];
#pragma unroll
    for (int l = 0; l < 32; ++l)
        a[l] = __fadd_rn(__fmul_rn(x[l], x[l]),
                         __fmul_rn(x[l + 32], x[l + 32]));
#pragma unroll
    for (int off = 16; off >= 1; off >>= 1) {
#pragma unroll
        for (int l = 0; l < 16; ++l)
            if (l < off)
                a[l] = __fadd_rn(a[l], a[l + off]);
    }
    return a[0];
}

// ---------------------------------------------------------------------------
// Kernel 0: ref squared norms (fp32, pass-1 filter only).
// ---------------------------------------------------------------------------
__global__ void r2_kernel(const float* __restrict__ ref) {
    int i = blockIdx.x * blockDim.x + threadIdx.x;
    if (i >= NB * NR) return;
    const float4* p = reinterpret_cast<const float4*>(ref + (size_t)i * DIM);
    float s = 0.f;
#pragma unroll
    for (int j = 0; j < DIM / 4; ++j) {
        float4 v = p[j];
        s += v.x * v.x + v.y * v.y + v.z * v.z + v.w * v.w;
    }
    g_r2[i] = s;
}

// ---------------------------------------------------------------------------
// Kernel 1: tensor-core candidate generation. Grid (NQ/QPB, NSPLIT, NB),
// 128 threads (4 warps). Q tile resident as -2*q (so MMA yields -2*dot);
// 64-ref tiles double-buffered via cp.async; wmma tf32 m16n16k8; score tile
// stored col-major; thread-per-query scan with s = r2[r] + score, feeding the
// verified smem max-replace top-KC. Candidate SET only — rerank fixes order.
// ---------------------------------------------------------------------------
__global__ __launch_bounds__(QPB)
void knn_mma(const float* __restrict__ ref, const float* __restrict__ query) {
    extern __shared__ float sm[];
    float*          s_q     = sm + OFF_Q;
    float*          s_ref   = sm + OFF_REF;     // [2][TRR*DIM]
    float*          s_r2t   = sm + OFF_R2T;     // [2][TRR]
    float*          s_score = sm + OFF_SCORE;   // [TRR][QPB] col-major
    float*          s_val   = sm + OFF_VAL;     // [KC][QPB]
    unsigned short* s_idx   = reinterpret_cast<unsigned short*>(sm + OFF_IDX);

    const int b     = blockIdx.z;
    const int split = blockIdx.y;
    const int qc    = blockIdx.x;
    const int tid   = threadIdx.x;
    const int wid   = tid >> 5;

    // Load -2 * query tile (row-major, lda=DIM), fully coalesced.
    const float* qbase = query + ((size_t)b * NQ + (size_t)qc * QPB) * DIM;
#pragma unroll
    for (int i = 0; i < (QPB * DIM) / QPB; ++i)
        s_q[i * QPB + tid] = -2.f * qbase[i * QPB + tid];

    // Init selection buffers.
#pragma unroll
    for (int j = 0; j < KC; ++j) { s_val[j * QPB + tid] = CUDART_INF_F; s_idx[j * QPB + tid] = 0; }
    float mval  = CUDART_INF_F;
    int   mslot = 0;

    const float* refb  = ref + (size_t)b * NR * DIM;
    const float* r2b   = g_r2 + b * NR;
    const int    base0 = split * RPS;

    // Prologue: async-load tile 0 (TRR*DIM floats = 1024 float4, 8/thread).
    {
#pragma unroll
        for (int j = 0; j < (TRR * DIM / 4) / QPB; ++j)
            cp16((unsigned int)__cvta_generic_to_shared(&s_ref[0 * TRR * DIM + 4 * (j * QPB + tid)]),
                 refb + (size_t)base0 * DIM + 4 * (j * QPB + tid));
        if (tid < TRR)
            cp4((unsigned int)__cvta_generic_to_shared(&s_r2t[0 * TRR + tid]), r2b + base0 + tid);
        cp_commit();
        cp_wait0();
    }
    __syncthreads();

    for (int t = 0; t < NTILE; ++t) {
        const int buf   = t & 1;
        const int rbase = base0 + t * TRR;

        // Prefetch next tile into the other buffer (overlaps MMA + scan).
        if (t + 1 < NTILE) {
            const int nb_   = (t + 1) & 1;
            const int nbase = base0 + (t + 1) * TRR;
#pragma unroll
            for (int j = 0; j < (TRR * DIM / 4) / QPB; ++j)
                cp16((unsigned int)__cvta_generic_to_shared(&s_ref[nb_ * TRR * DIM + 4 * (j * QPB + tid)]),
                     refb + (size_t)nbase * DIM + 4 * (j * QPB + tid));
            if (tid < TRR)
                cp4((unsigned int)__cvta_generic_to_shared(&s_r2t[nb_ * TRR + tid]), r2b + nbase + tid);
            cp_commit();
        }

        // MMA: warp wid owns query rows [wid*32, wid*32+32) = 2 m-subtiles;
        // 4 n-subtiles of 16 refs each; 8 k-steps of 8.
        {
            wmma::fragment<wmma::accumulator, 16, 16, 8, float> acc[2][4];
#pragma unroll
            for (int mi = 0; mi < 2; ++mi)
#pragma unroll
                for (int ni = 0; ni < 4; ++ni)
                    wmma::fill_fragment(acc[mi][ni], 0.f);

#pragma unroll
            for (int k = 0; k < 8; ++k) {
                wmma::fragment<wmma::matrix_a, 16, 16, 8, wmma::precision::tf32, wmma::row_major> af[2];
                wmma::fragment<wmma::matrix_b, 16, 16, 8, wmma::precision::tf32, wmma::col_major> bf[4];
#pragma unroll
                for (int mi = 0; mi < 2; ++mi) {
                    wmma::load_matrix_sync(af[mi], s_q + (wid * 32 + mi * 16) * DIM + k * 8, DIM);
#pragma unroll
                    for (int e = 0; e < af[mi].num_elements; ++e)
                        af[mi].x[e] = wmma::__float_to_tf32(af[mi].x[e]);
                }
#pragma unroll
                for (int ni = 0; ni < 4; ++ni) {
                    // B col-major: element (kk, nn) at base[nn*DIM + kk] == ref row-major
                    wmma::load_matrix_sync(bf[ni], s_ref + buf * TRR * DIM + (ni * 16) * DIM + k * 8, DIM);
#pragma unroll
                    for (int e = 0; e < bf[ni].num_elements; ++e)
                        bf[ni].x[e] = wmma::__float_to_tf32(bf[ni].x[e]);
                }
#pragma unroll
                for (int mi = 0; mi < 2; ++mi)
#pragma unroll
                    for (int ni = 0; ni < 4; ++ni)
                        wmma::mma_sync(acc[mi][ni], af[mi], bf[ni], acc[mi][ni]);
            }
            // Store col-major: score[(n)*QPB + m]
#pragma unroll
            for (int mi = 0; mi < 2; ++mi)
#pragma unroll
                for (int ni = 0; ni < 4; ++ni)
                    wmma::store_matrix_sync(s_score + (ni * 16) * QPB + (wid * 32 + mi * 16),
                                            acc[mi][ni], QPB, wmma::mem_col_major);
        }
        __syncthreads();

        // Scan: thread tid = query. s = r2[r] + (-2*dot). Conflict-free LDS.
        for (int r = 0; r < TRR; ++r) {
            float s = s_r2t[buf * TRR + r] + s_score[r * QPB + tid];
            if (s < mval) {
                s_val[mslot * QPB + tid] = s;
                s_idx[mslot * QPB + tid] = (unsigned short)(rbase + r);
                float nm = -CUDART_INF_F; int ns = 0;
#pragma unroll
                for (int j = 0; j < KC; ++j) {
                    float v = s_val[j * QPB + tid];
                    if (v > nm) { nm = v; ns = j; }
                }
                mval = nm; mslot = ns;
            }
        }

        cp_wait0();
        __syncthreads();
    }

    const int q = qc * QPB + tid;
    const size_t o = (((size_t)b * NQ + q) * NSPLIT + split) * KC;
#pragma unroll
    for (int j = 0; j < KC; ++j) g_cand[o + j] = (int)s_idx[j * QPB + tid];
}

// ---------------------------------------------------------------------------
// Kernel 2: BIT-EXACT reference emulation + final select (VERIFIED in R8).
//   dot   = single sequential fused-FMA chain, k ascending (cuBLAS SGEMM)
//   r2,q2 = XLA warp row-reduction (strided lane accum + shfl tree)
//   key   = max( fl( fl(q2+r2) - fl(2*dot) ), 0 )
// Select 16 by lexicographic (key, idx) == top_k's stable tie-break.
// Candidate order in g_cand is irrelevant (pure set).
// ---------------------------------------------------------------------------
__global__ void knn_rerank(const float* __restrict__ ref,
                           const float* __restrict__ query,
                           float* __restrict__ outD, float* __restrict__ outI) {
    int gq = blockIdx.x * blockDim.x + threadIdx.x;
    if (gq >= NB * NQ) return;
    const int b = gq / NQ;

    const float4* qp = reinterpret_cast<const float4*>(query + (size_t)gq * DIM);
    float qv[DIM];
#pragma unroll
    for (int j = 0; j < DIM / 4; ++j) {
        float4 v = qp[j];
        qv[4 * j + 0] = v.x; qv[4 * j + 1] = v.y;
        qv[4 * j + 2] = v.z; qv[4 * j + 3] = v.w;
    }
    const float q2f = xla_row_sumsq(qv);

    float dk[KK];
    int   ik[KK];
#pragma unroll
    for (int j = 0; j < KK; ++j) { dk[j] = CUDART_INF_F; ik[j] = 0x7FFFFFFF; }

    const int* cand = g_cand + (size_t)gq * NCAND;
    const float4* refb = reinterpret_cast<const float4*>(ref + (size_t)b * NR * DIM);

    for (int c = 0; c < NCAND; ++c) {
        const int idx = cand[c];
        const float4* rp = refb + (size_t)idx * (DIM / 4);
        float rv[DIM];
#pragma unroll
        for (int j = 0; j < DIM / 4; ++j) {
            float4 v = rp[j];
            rv[4 * j + 0] = v.x; rv[4 * j + 1] = v.y;
            rv[4 * j + 2] = v.z; rv[4 * j + 3] = v.w;
        }
        float dotf = 0.f;
#pragma unroll
        for (int k = 0; k < DIM; ++k)
            dotf = fmaf(qv[k], rv[k], dotf);
        const float r2f = xla_row_sumsq(rv);

        const float s12 = __fadd_rn(q2f, r2f);
        const float t2d = __fmul_rn(2.0f, dotf);
        const float key = fmaxf(__fadd_rn(s12, -t2d), 0.f);

        bool better_last = (key < dk[KK - 1]) ||
                           (key == dk[KK - 1] && idx < ik[KK - 1]);
        if (better_last) {
#pragma unroll
            for (int j = KK - 1; j >= 0; --j) {
                bool lt_prev = (j > 0) &&
                    ((key < dk[j - 1]) || (key == dk[j - 1] && idx < ik[j - 1]));
                bool lt_here = (key < dk[j]) || (key == dk[j] && idx < ik[j]);
                if (lt_prev)      { dk[j] = dk[j - 1]; ik[j] = ik[j - 1]; }
                else if (lt_here) { dk[j] = key;       ik[j] = idx;       }
            }
        }
    }

#pragma unroll
    for (int j = 0; j < KK; ++j) {
        outD[(size_t)gq * KK + j] = sqrtf(dk[j]);
        outI[(size_t)gq * KK + j] = (float)ik[j];
    }
}

// ---------------------------------------------------------------------------
// Launch: ref = d_in[0], query = d_in[1].
// d_out layout: D [NB*NQ*KK] f32, then I [NB*NQ*KK] f32 (single output dtype).
// ---------------------------------------------------------------------------
extern "C" void kernel_launch(void* const* d_in, const int* in_sizes, int n_in,
                              void* d_out, int out_size) {
    const float* ref   = (const float*)d_in[0];
    const float* query = (const float*)d_in[1];

    float* outD = (float*)d_out;
    float* outI = (float*)d_out + (size_t)NB * NQ * KK;

    // Idempotent attribute set (dynamic smem 111.5 KB > 48 KB default).
    cudaFuncSetAttribute(knn_mma, cudaFuncAttributeMaxDynamicSharedMemorySize, SMEM_BYTES);

    r2_kernel<<<(NB * NR + 255) / 256, 256>>>(ref);
    knn_mma<<<dim3(NQ / QPB, NSPLIT, NB), QPB, SMEM_BYTES>>>(ref, query);
    knn_rerank<<<(NB * NQ + 63) / 64, 64>>>(ref, query, outD, outI);
}

// round 11
// speedup vs baseline: 1.2864x; 1.2864x over previous
#include <cuda_runtime.h>
#include <math_constants.h>
#include <mma.h>

using namespace nvcuda;

// Problem shape (fixed by the dataset)
#define NB 4
#define NQ 2048
#define NR 16384
#define DIM 64
#define KK 16
#define KC 20                   // candidates kept per split (margin over KK)
#define NSPLIT 4
#define QPB 128                 // queries per block
#define TRR 64                  // refs per tile
#define RPS (NR / NSPLIT)       // 4096 refs per split
#define NTILE (RPS / TRR)       // 64 tiles per split
#define NCAND (NSPLIT * KC)     // 80 candidates per query

#define LDB 68                  // padded ref-tile row (floats): 2-way max conflicts
#define LDS_SC 132              // padded score ldm: conflict-free scan

// Dynamic smem layout (floats). s_q ALIASES s_score (q dead after prologue).
#define OFF_SCORE 0
#define SCORE_SZ  (TRR * LDS_SC)            // 8448
#define OFF_Q     0                          // alias (8192 <= 8448)
#define OFF_REF   SCORE_SZ                   // 8448
#define REF_SZ    (2 * TRR * LDB)            // 8704
#define OFF_R2T   (OFF_REF + REF_SZ)         // 17152
#define OFF_VAL   (OFF_R2T + 2 * TRR)        // 17280
#define OFF_IDX   (OFF_VAL + KC * QPB)       // 19840
#define SMEM_FLOATS (OFF_IDX + (KC * QPB) / 2)
#define SMEM_BYTES  (SMEM_FLOATS * 4)        // 84480 B -> 2 blocks/SM

// Scratch (device globals: harness forbids cudaMalloc)
__device__ float g_r2[NB * NR];
__device__ int   g_cand[(size_t)NB * NQ * NCAND];

// cp.async helpers
__device__ __forceinline__ void cp16(unsigned int dst, const void* src) {
    asm volatile("cp.async.cg.shared.global [%0], [%1], 16;" :: "r"(dst), "l"(src));
}
__device__ __forceinline__ void cp4(unsigned int dst, const void* src) {
    asm volatile("cp.async.ca.shared.global [%0], [%1], 4;" :: "r"(dst), "l"(src));
}
__device__ __forceinline__ void cp_commit() { asm volatile("cp.async.commit_group;"); }
__device__ __forceinline__ void cp_wait0()  { asm volatile("cp.async.wait_group 0;" ::: "memory"); }

// ---------------------------------------------------------------------------
// XLA-GPU row-reduction emulation for sum(x*x) over 64 elements (verified
// bit-exact vs reference in R8): strided lane accum + shfl_down tree.
// ---------------------------------------------------------------------------
__device__ __forceinline__ float xla_row_sumsq(const float* __restrict__ x) {
    float a[32];
#pragma unroll
    for (int l = 0; l < 32; ++l)
        a[l] = __fadd_rn(__fmul_rn(x[l], x[l]),
                         __fmul_rn(x[l + 32], x[l + 32]));
#pragma unroll
    for (int off = 16; off >= 1; off >>= 1) {
#pragma unroll
        for (int l = 0; l < 16; ++l)
            if (l < off)
                a[l] = __fadd_rn(a[l], a[l + off]);
    }
    return a[0];
}

// ---------------------------------------------------------------------------
// Kernel 0: ref squared norms (fp32, pass-1 filter only).
// ---------------------------------------------------------------------------
__global__ void r2_kernel(const float* __restrict__ ref) {
    int i = blockIdx.x * blockDim.x + threadIdx.x;
    if (i >= NB * NR) return;
    const float4* p = reinterpret_cast<const float4*>(ref + (size_t)i * DIM);
    float s = 0.f;
#pragma unroll
    for (int j = 0; j < DIM / 4; ++j) {
        float4 v = p[j];
        s += v.x * v.x + v.y * v.y + v.z * v.z + v.w * v.w;
    }
    g_r2[i] = s;
}

// Phase-shift no-op so ncu -s 5 lands on knn_mma next round.
__global__ void nop_kernel() {}

// ---------------------------------------------------------------------------
// Kernel 1: tensor-core candidate generation (tf32 wmma), conflict-fixed.
// Grid (NQ/QPB, NSPLIT, NB), 128 threads (4 warps).
//  - A (= -2*query tile) fragments hoisted into registers ONCE (tf32).
//  - Ref tiles double-buffered, rows padded to LDB=68 (2-way max conflicts).
//  - Score tile padded to LDS_SC=132 (conflict-free scan), aliases dead Q.
//  - Thread-per-query scan feeds verified smem max-replace top-KC (SET only).
// ---------------------------------------------------------------------------
__global__ __launch_bounds__(QPB)
void knn_mma(const float* __restrict__ ref, const float* __restrict__ query) {
    extern __shared__ float sm[];
    float*          s_score = sm + OFF_SCORE;   // [TRR][LDS_SC]
    float*          s_q     = sm + OFF_Q;       // alias of s_score (prologue only)
    float*          s_ref   = sm + OFF_REF;     // [2][TRR][LDB]
    float*          s_r2t   = sm + OFF_R2T;     // [2][TRR]
    float*          s_val   = sm + OFF_VAL;     // [KC][QPB]
    unsigned short* s_idx   = reinterpret_cast<unsigned short*>(sm + OFF_IDX);

    const int b     = blockIdx.z;
    const int split = blockIdx.y;
    const int qc    = blockIdx.x;
    const int tid   = threadIdx.x;
    const int wid   = tid >> 5;

    // --- Prologue: load -2*q tile, build persistent A fragments ---
    const float* qbase = query + ((size_t)b * NQ + (size_t)qc * QPB) * DIM;
#pragma unroll
    for (int i = 0; i < DIM; ++i)
        s_q[i * QPB + tid] = -2.f * qbase[i * QPB + tid];

    // Init selection buffers (val region does not alias q/score).
#pragma unroll
    for (int j = 0; j < KC; ++j) { s_val[j * QPB + tid] = CUDART_INF_F; s_idx[j * QPB + tid] = 0; }
    float mval  = CUDART_INF_F;
    int   mslot = 0;

    const float* refb  = ref + (size_t)b * NR * DIM;
    const float* r2b   = g_r2 + b * NR;
    const int    base0 = split * RPS;

    // Async-load tile 0 into padded rows while q tile settles.
#pragma unroll
    for (int j = 0; j < (TRR * DIM / 4) / QPB; ++j) {
        int idx4 = j * QPB + tid;            // flat float4 index, 1024 total
        int row  = idx4 >> 4;                // /16
        int c4   = idx4 & 15;
        cp16((unsigned int)__cvta_generic_to_shared(&s_ref[row * LDB + c4 * 4]),
             refb + (size_t)base0 * DIM + idx4 * 4);
    }
    if (tid < TRR)
        cp4((unsigned int)__cvta_generic_to_shared(&s_r2t[tid]), r2b + base0 + tid);
    cp_commit();
    __syncthreads();   // q tile visible to all warps

    // Persistent A fragments: 2 m-subtiles x 8 k-steps, converted to tf32 once.
    wmma::fragment<wmma::matrix_a, 16, 16, 8, wmma::precision::tf32, wmma::row_major> af[2][8];
#pragma unroll
    for (int mi = 0; mi < 2; ++mi)
#pragma unroll
        for (int k = 0; k < 8; ++k) {
            wmma::load_matrix_sync(af[mi][k], s_q + (wid * 32 + mi * 16) * DIM + k * 8, DIM);
#pragma unroll
            for (int e = 0; e < af[mi][k].num_elements; ++e)
                af[mi][k].x[e] = wmma::__float_to_tf32(af[mi][k].x[e]);
        }
    cp_wait0();
    __syncthreads();   // frags built everywhere; q region may now be clobbered

    for (int t = 0; t < NTILE; ++t) {
        const int buf   = t & 1;
        const int rbase = base0 + t * TRR;

        // Prefetch next tile (overlaps MMA + scan).
        if (t + 1 < NTILE) {
            const int nb_   = (t + 1) & 1;
            const int nbase = base0 + (t + 1) * TRR;
#pragma unroll
            for (int j = 0; j < (TRR * DIM / 4) / QPB; ++j) {
                int idx4 = j * QPB + tid;
                int row  = idx4 >> 4;
                int c4   = idx4 & 15;
                cp16((unsigned int)__cvta_generic_to_shared(&s_ref[nb_ * TRR * LDB + row * LDB + c4 * 4]),
                     refb + (size_t)nbase * DIM + idx4 * 4);
            }
            if (tid < TRR)
                cp4((unsigned int)__cvta_generic_to_shared(&s_r2t[nb_ * TRR + tid]), r2b + nbase + tid);
            cp_commit();
        }

        // MMA: B loads only (A is register-resident). 4 n-subtiles, 8 k-steps.
        {
            wmma::fragment<wmma::accumulator, 16, 16, 8, float> acc[2][4];
#pragma unroll
            for (int mi = 0; mi < 2; ++mi)
#pragma unroll
                for (int ni = 0; ni < 4; ++ni)
                    wmma::fill_fragment(acc[mi][ni], 0.f);

#pragma unroll
            for (int k = 0; k < 8; ++k) {
                wmma::fragment<wmma::matrix_b, 16, 16, 8, wmma::precision::tf32, wmma::col_major> bf[4];
#pragma unroll
                for (int ni = 0; ni < 4; ++ni) {
                    wmma::load_matrix_sync(bf[ni],
                        s_ref + buf * TRR * LDB + (ni * 16) * LDB + k * 8, LDB);
#pragma unroll
                    for (int e = 0; e < bf[ni].num_elements; ++e)
                        bf[ni].x[e] = wmma::__float_to_tf32(bf[ni].x[e]);
                }
#pragma unroll
                for (int mi = 0; mi < 2; ++mi)
#pragma unroll
                    for (int ni = 0; ni < 4; ++ni)
                        wmma::mma_sync(acc[mi][ni], af[mi][k], bf[ni], acc[mi][ni]);
            }
#pragma unroll
            for (int mi = 0; mi < 2; ++mi)
#pragma unroll
                for (int ni = 0; ni < 4; ++ni)
                    wmma::store_matrix_sync(s_score + (ni * 16) * LDS_SC + (wid * 32 + mi * 16),
                                            acc[mi][ni], LDS_SC, wmma::mem_col_major);
        }
        __syncthreads();

        // Scan: thread tid = query. s = r2[r] + (-2*dot). Conflict-free LDS.
        for (int r = 0; r < TRR; ++r) {
            float s = s_r2t[buf * TRR + r] + s_score[r * LDS_SC + tid];
            if (s < mval) {
                s_val[mslot * QPB + tid] = s;
                s_idx[mslot * QPB + tid] = (unsigned short)(rbase + r);
                float nm = -CUDART_INF_F; int ns = 0;
#pragma unroll
                for (int j = 0; j < KC; ++j) {
                    float v = s_val[j * QPB + tid];
                    if (v > nm) { nm = v; ns = j; }
                }
                mval = nm; mslot = ns;
            }
        }

        cp_wait0();
        __syncthreads();
    }

    const int q = qc * QPB + tid;
    const size_t o = (((size_t)b * NQ + q) * NSPLIT + split) * KC;
#pragma unroll
    for (int j = 0; j < KC; ++j) g_cand[o + j] = (int)s_idx[j * QPB + tid];
}

// ---------------------------------------------------------------------------
// Kernel 2: BIT-EXACT reference emulation + final select (VERIFIED in R8).
//   dot   = single sequential fused-FMA chain, k ascending (cuBLAS SGEMM)
//   r2,q2 = XLA warp row-reduction (strided lane accum + shfl tree)
//   key   = max( fl( fl(q2+r2) - fl(2*dot) ), 0 )
// Select 16 by lexicographic (key, idx) == top_k's stable tie-break.
// ---------------------------------------------------------------------------
__global__ void knn_rerank(const float* __restrict__ ref,
                           const float* __restrict__ query,
                           float* __restrict__ outD, float* __restrict__ outI) {
    int gq = blockIdx.x * blockDim.x + threadIdx.x;
    if (gq >= NB * NQ) return;
    const int b = gq / NQ;

    const float4* qp = reinterpret_cast<const float4*>(query + (size_t)gq * DIM);
    float qv[DIM];
#pragma unroll
    for (int j = 0; j < DIM / 4; ++j) {
        float4 v = qp[j];
        qv[4 * j + 0] = v.x; qv[4 * j + 1] = v.y;
        qv[4 * j + 2] = v.z; qv[4 * j + 3] = v.w;
    }
    const float q2f = xla_row_sumsq(qv);

    float dk[KK];
    int   ik[KK];
#pragma unroll
    for (int j = 0; j < KK; ++j) { dk[j] = CUDART_INF_F; ik[j] = 0x7FFFFFFF; }

    const int* cand = g_cand + (size_t)gq * NCAND;
    const float4* refb = reinterpret_cast<const float4*>(ref + (size_t)b * NR * DIM);

    for (int c = 0; c < NCAND; ++c) {
        const int idx = cand[c];
        const float4* rp = refb + (size_t)idx * (DIM / 4);
        float rv[DIM];
#pragma unroll
        for (int j = 0; j < DIM / 4; ++j) {
            float4 v = rp[j];
            rv[4 * j + 0] = v.x; rv[4 * j + 1] = v.y;
            rv[4 * j + 2] = v.z; rv[4 * j + 3] = v.w;
        }
        float dotf = 0.f;
#pragma unroll
        for (int k = 0; k < DIM; ++k)
            dotf = fmaf(qv[k], rv[k], dotf);
        const float r2f = xla_row_sumsq(rv);

        const float s12 = __fadd_rn(q2f, r2f);
        const float t2d = __fmul_rn(2.0f, dotf);
        const float key = fmaxf(__fadd_rn(s12, -t2d), 0.f);

        bool better_last = (key < dk[KK - 1]) ||
                           (key == dk[KK - 1] && idx < ik[KK - 1]);
        if (better_last) {
#pragma unroll
            for (int j = KK - 1; j >= 0; --j) {
                bool lt_prev = (j > 0) &&
                    ((key < dk[j - 1]) || (key == dk[j - 1] && idx < ik[j - 1]));
                bool lt_here = (key < dk[j]) || (key == dk[j] && idx < ik[j]);
                if (lt_prev)      { dk[j] = dk[j - 1]; ik[j] = ik[j - 1]; }
                else if (lt_here) { dk[j] = key;       ik[j] = idx;       }
            }
        }
    }

#pragma unroll
    for (int j = 0; j < KK; ++j) {
        outD[(size_t)gq * KK + j] = sqrtf(dk[j]);
        outI[(size_t)gq * KK + j] = (float)ik[j];
    }
}

// ---------------------------------------------------------------------------
// Launch: ref = d_in[0], query = d_in[1].
// d_out layout: D [NB*NQ*KK] f32, then I [NB*NQ*KK] f32 (single output dtype).
// ---------------------------------------------------------------------------
extern "C" void kernel_launch(void* const* d_in, const int* in_sizes, int n_in,
                              void* d_out, int out_size) {
    const float* ref   = (const float*)d_in[0];
    const float* query = (const float*)d_in[1];

    float* outD = (float*)d_out;
    float* outI = (float*)d_out + (size_t)NB * NQ * KK;

    cudaFuncSetAttribute(knn_mma, cudaFuncAttributeMaxDynamicSharedMemorySize, SMEM_BYTES);

    r2_kernel<<<(NB * NR + 255) / 256, 256>>>(ref);
    knn_mma<<<dim3(NQ / QPB, NSPLIT, NB), QPB, SMEM_BYTES>>>(ref, query);
    knn_rerank<<<(NB * NQ + 63) / 64, 64>>>(ref, query, outD, outI);
    nop_kernel<<<1, 32>>>();   // phase-shift so ncu -s 5 profiles knn_mma
}

// round 13
// speedup vs baseline: 1.6259x; 1.2639x over previous
#include <cuda_runtime.h>
#include <cuda_bf16.h>
#include <math_constants.h>
#include <mma.h>

using namespace nvcuda;

// Problem shape (fixed by the dataset)
#define NB 4
#define NQ 2048
#define NR 16384
#define DIM 64
#define KK 16
#define KC 20                   // candidates kept per split (margin over KK)
#define NSPLIT 4
#define QPB 128                 // queries per block
#define TRR 64                  // refs per tile
#define RPS (NR / NSPLIT)       // 4096 refs per split
#define NTILE (RPS / TRR)       // 64 tiles per split
#define NCAND (NSPLIT * KC)     // 80 candidates per query

#define LDA_BF 72               // padded bf16 q-tile row (ldmatrix conflict-free)
#define LDB_BF 72               // padded bf16 ref-tile row
#define LDS_SC 132              // padded score ldm: conflict-free scan

// Dynamic smem layout (float units). Q tile (bf16) ALIASES score tile.
#define OFF_SCORE 0
#define SCORE_SZ  (TRR * LDS_SC)                    // 8448 floats
#define OFF_REF   SCORE_SZ                          // bf16 [2][TRR][LDB_BF] = 4608 floats
#define REF_SZ    ((2 * TRR * LDB_BF) / 2)
#define OFF_R2T   (OFF_REF + REF_SZ)                // [2][TRR]
#define OFF_VAL   (OFF_R2T + 2 * TRR)               // [KC][QPB]
#define OFF_IDX   (OFF_VAL + KC * QPB)              // u16 [KC][QPB]
#define SMEM_FLOATS (OFF_IDX + (KC * QPB) / 2)
#define SMEM_BYTES  (SMEM_FLOATS * 4)               // 68096 B -> 2 blocks/SM

// Scratch (device globals: harness forbids cudaMalloc)
__device__ float          g_r2[NB * NR];
__device__ __nv_bfloat16  g_ref_bf16[(size_t)NB * NR * DIM];
__device__ int            g_cand[(size_t)NB * NQ * NCAND];

// cp.async helpers
__device__ __forceinline__ void cp16(unsigned int dst, const void* src) {
    asm volatile("cp.async.cg.shared.global [%0], [%1], 16;" :: "r"(dst), "l"(src));
}
__device__ __forceinline__ void cp4(unsigned int dst, const void* src) {
    asm volatile("cp.async.ca.shared.global [%0], [%1], 4;" :: "r"(dst), "l"(src));
}
__device__ __forceinline__ void cp_commit() { asm volatile("cp.async.commit_group;"); }
__device__ __forceinline__ void cp_wait0()  { asm volatile("cp.async.wait_group 0;" ::: "memory"); }

// ---------------------------------------------------------------------------
// XLA-GPU row-reduction emulation for sum(x*x) over 64 elements (verified
// bit-exact vs reference in R8): strided lane accum + shfl_down tree.
// ---------------------------------------------------------------------------
__device__ __forceinline__ float xla_row_sumsq(const float* __restrict__ x) {
    float a[32];
#pragma unroll
    for (int l = 0; l < 32; ++l)
        a[l] = __fadd_rn(__fmul_rn(x[l], x[l]),
                         __fmul_rn(x[l + 32], x[l + 32]));
#pragma unroll
    for (int off = 16; off >= 1; off >>= 1) {
#pragma unroll
        for (int l = 0; l < 16; ++l)
            if (l < off)
                a[l] = __fadd_rn(a[l], a[l + off]);
    }
    return a[0];
}

// ---------------------------------------------------------------------------
// Kernel 0a: ref squared norms (exact f32, pass-1 filter only).
// ---------------------------------------------------------------------------
__global__ void r2_kernel(const float* __restrict__ ref) {
    int i = blockIdx.x * blockDim.x + threadIdx.x;
    if (i >= NB * NR) return;
    const float4* p = reinterpret_cast<const float4*>(ref + (size_t)i * DIM);
    float s = 0.f;
#pragma unroll
    for (int j = 0; j < DIM / 4; ++j) {
        float4 v = p[j];
        s += v.x * v.x + v.y * v.y + v.z * v.z + v.w * v.w;
    }
    g_r2[i] = s;
}

// ---------------------------------------------------------------------------
// Kernel 0b: ref f32 -> bf16 (one-time; removes all per-tile CVTs).
// ---------------------------------------------------------------------------
__global__ void cvt_kernel(const float* __restrict__ ref) {
    int i = blockIdx.x * blockDim.x + threadIdx.x;          // bf16x2 pair index
    if (i >= NB * NR * DIM / 2) return;
    const float2 v = reinterpret_cast<const float2*>(ref)[i];
    reinterpret_cast<__nv_bfloat162*>(g_ref_bf16)[i] = __float22bfloat162_rn(v);
}

// Launch-slot spacer (keeps knn_mma on the profiled slot; see launch order).
__global__ void nop_kernel() {}

// ---------------------------------------------------------------------------
// Kernel 1: bf16 tensor-core candidate generation. Grid (NQ/QPB, NSPLIT, NB),
// 128 threads (4 warps).
//  - A (= -2*query, bf16) fragments hoisted into registers ONCE.
//  - Ref tiles (bf16, pre-converted) double-buffered via cp.async, rows padded
//    to 72 elements (144 B) -> ldmatrix conflict-free.
//  - wmma m16n16k16 bf16, fp32 accum; score tile padded to LDS_SC=132.
//  - Thread-per-query scan feeds verified smem max-replace top-KC (SET only;
//    the bit-exact rerank kernel re-derives order/values from f32 data).
// ---------------------------------------------------------------------------
__global__ __launch_bounds__(QPB)
void knn_mma(const float* __restrict__ query) {
    extern __shared__ float sm[];
    float*          s_score = sm + OFF_SCORE;                         // [TRR][LDS_SC]
    __nv_bfloat16*  s_q     = reinterpret_cast<__nv_bfloat16*>(sm);   // alias (prologue)
    __nv_bfloat16*  s_ref   = reinterpret_cast<__nv_bfloat16*>(sm + OFF_REF); // [2][TRR][LDB_BF]
    float*          s_r2t   = sm + OFF_R2T;                           // [2][TRR]
    float*          s_val   = sm + OFF_VAL;                           // [KC][QPB]
    unsigned short* s_idx   = reinterpret_cast<unsigned short*>(sm + OFF_IDX);

    const int b     = blockIdx.z;
    const int split = blockIdx.y;
    const int qc    = blockIdx.x;
    const int tid   = threadIdx.x;
    const int wid   = tid >> 5;

    // --- Prologue: -2*q tile in bf16 (row-major, lda=LDA_BF) ---
    const float* qbase = query + ((size_t)b * NQ + (size_t)qc * QPB) * DIM;
#pragma unroll
    for (int j = 0; j < (QPB * DIM) / QPB; ++j) {
        int idx = j * QPB + tid;            // flat, coalesced
        int row = idx >> 6, col = idx & 63;
        s_q[row * LDA_BF + col] = __float2bfloat16(-2.f * qbase[idx]);
    }

    // Init selection buffers.
#pragma unroll
    for (int j = 0; j < KC; ++j) { s_val[j * QPB + tid] = CUDART_INF_F; s_idx[j * QPB + tid] = 0; }
    float mval  = CUDART_INF_F;
    int   mslot = 0;

    const __nv_bfloat16* refb = g_ref_bf16 + (size_t)b * NR * DIM;
    const float*         r2b  = g_r2 + b * NR;
    const int            base0 = split * RPS;

    // Async-load tile 0 (64 rows x 128 B of bf16 = 512 cp16, 4/thread).
#pragma unroll
    for (int j = 0; j < 4; ++j) {
        int idx16 = j * QPB + tid;          // 16-byte chunk index
        int row   = idx16 >> 3;
        int c     = idx16 & 7;
        cp16((unsigned int)__cvta_generic_to_shared(&s_ref[row * LDB_BF + c * 8]),
             refb + (size_t)base0 * DIM + idx16 * 8);
    }
    if (tid < TRR)
        cp4((unsigned int)__cvta_generic_to_shared(&s_r2t[tid]), r2b + base0 + tid);
    cp_commit();
    __syncthreads();   // q tile visible

    // Persistent A fragments: 2 m-subtiles x 4 k-steps (bf16, k=16).
    wmma::fragment<wmma::matrix_a, 16, 16, 16, __nv_bfloat16, wmma::row_major> af[2][4];
#pragma unroll
    for (int mi = 0; mi < 2; ++mi)
#pragma unroll
        for (int k = 0; k < 4; ++k)
            wmma::load_matrix_sync(af[mi][k],
                s_q + (wid * 32 + mi * 16) * LDA_BF + k * 16, LDA_BF);
    cp_wait0();
    __syncthreads();   // frags built; q region (aliased by score) may be clobbered

    for (int t = 0; t < NTILE; ++t) {
        const int buf   = t & 1;
        const int rbase = base0 + t * TRR;

        // Prefetch next tile (overlaps MMA + scan).
        if (t + 1 < NTILE) {
            const int nb_   = (t + 1) & 1;
            const int nbase = base0 + (t + 1) * TRR;
#pragma unroll
            for (int j = 0; j < 4; ++j) {
                int idx16 = j * QPB + tid;
                int row   = idx16 >> 3;
                int c     = idx16 & 7;
                cp16((unsigned int)__cvta_generic_to_shared(
                         &s_ref[nb_ * TRR * LDB_BF + row * LDB_BF + c * 8]),
                     refb + (size_t)nbase * DIM + idx16 * 8);
            }
            if (tid < TRR)
                cp4((unsigned int)__cvta_generic_to_shared(&s_r2t[nb_ * TRR + tid]),
                    r2b + nbase + tid);
            cp_commit();
        }

        // MMA: B loads only (A register-resident). 4 n-subtiles, 4 k-steps.
        {
            wmma::fragment<wmma::accumulator, 16, 16, 16, float> acc[2][4];
#pragma unroll
            for (int mi = 0; mi < 2; ++mi)
#pragma unroll
                for (int ni = 0; ni < 4; ++ni)
                    wmma::fill_fragment(acc[mi][ni], 0.f);

#pragma unroll
            for (int k = 0; k < 4; ++k) {
                wmma::fragment<wmma::matrix_b, 16, 16, 16, __nv_bfloat16, wmma::col_major> bf[4];
#pragma unroll
                for (int ni = 0; ni < 4; ++ni)
                    wmma::load_matrix_sync(bf[ni],
                        s_ref + buf * TRR * LDB_BF + (ni * 16) * LDB_BF + k * 16, LDB_BF);
#pragma unroll
                for (int mi = 0; mi < 2; ++mi)
#pragma unroll
                    for (int ni = 0; ni < 4; ++ni)
                        wmma::mma_sync(acc[mi][ni], af[mi][k], bf[ni], acc[mi][ni]);
            }
#pragma unroll
            for (int mi = 0; mi < 2; ++mi)
#pragma unroll
                for (int ni = 0; ni < 4; ++ni)
                    wmma::store_matrix_sync(s_score + (ni * 16) * LDS_SC + (wid * 32 + mi * 16),
                                            acc[mi][ni], LDS_SC, wmma::mem_col_major);
        }
        __syncthreads();

        // Scan: thread tid = query. s = r2[r] + (-2*dot). Conflict-free LDS.
        for (int r = 0; r < TRR; ++r) {
            float s = s_r2t[buf * TRR + r] + s_score[r * LDS_SC + tid];
            if (s < mval) {
                s_val[mslot * QPB + tid] = s;
                s_idx[mslot * QPB + tid] = (unsigned short)(rbase + r);
                float nm = -CUDART_INF_F; int ns = 0;
#pragma unroll
                for (int j = 0; j < KC; ++j) {
                    float v = s_val[j * QPB + tid];
                    if (v > nm) { nm = v; ns = j; }
                }
                mval = nm; mslot = ns;
            }
        }

        cp_wait0();
        __syncthreads();
    }

    const int q = qc * QPB + tid;
    const size_t o = (((size_t)b * NQ + q) * NSPLIT + split) * KC;
#pragma unroll
    for (int j = 0; j < KC; ++j) g_cand[o + j] = (int)s_idx[j * QPB + tid];
}

// ---------------------------------------------------------------------------
// Kernel 2: BIT-EXACT reference emulation + final select (VERIFIED in R8).
//   dot   = single sequential fused-FMA chain, k ascending (cuBLAS SGEMM)
//   r2,q2 = XLA warp row-reduction (strided lane accum + shfl tree)
//   key   = max( fl( fl(q2+r2) - fl(2*dot) ), 0 )
// Select 16 by lexicographic (key, idx) == top_k's stable tie-break.
// ---------------------------------------------------------------------------
__global__ void knn_rerank(const float* __restrict__ ref,
                           const float* __restrict__ query,
                           float* __restrict__ outD, float* __restrict__ outI) {
    int gq = blockIdx.x * blockDim.x + threadIdx.x;
    if (gq >= NB * NQ) return;
    const int b = gq / NQ;

    const float4* qp = reinterpret_cast<const float4*>(query + (size_t)gq * DIM);
    float qv[DIM];
#pragma unroll
    for (int j = 0; j < DIM / 4; ++j) {
        float4 v = qp[j];
        qv[4 * j + 0] = v.x; qv[4 * j + 1] = v.y;
        qv[4 * j + 2] = v.z; qv[4 * j + 3] = v.w;
    }
    const float q2f = xla_row_sumsq(qv);

    float dk[KK];
    int   ik[KK];
#pragma unroll
    for (int j = 0; j < KK; ++j) { dk[j] = CUDART_INF_F; ik[j] = 0x7FFFFFFF; }

    const int* cand = g_cand + (size_t)gq * NCAND;
    const float4* refb = reinterpret_cast<const float4*>(ref + (size_t)b * NR * DIM);

    for (int c = 0; c < NCAND; ++c) {
        const int idx = cand[c];
        const float4* rp = refb + (size_t)idx * (DIM / 4);
        float rv[DIM];
#pragma unroll
        for (int j = 0; j < DIM / 4; ++j) {
            float4 v = rp[j];
            rv[4 * j + 0] = v.x; rv[4 * j + 1] = v.y;
            rv[4 * j + 2] = v.z; rv[4 * j + 3] = v.w;
        }
        float dotf = 0.f;
#pragma unroll
        for (int k = 0; k < DIM; ++k)
            dotf = fmaf(qv[k], rv[k], dotf);
        const float r2f = xla_row_sumsq(rv);

        const float s12 = __fadd_rn(q2f, r2f);
        const float t2d = __fmul_rn(2.0f, dotf);
        const float key = fmaxf(__fadd_rn(s12, -t2d), 0.f);

        bool better_last = (key < dk[KK - 1]) ||
                           (key == dk[KK - 1] && idx < ik[KK - 1]);
        if (better_last) {
#pragma unroll
            for (int j = KK - 1; j >= 0; --j) {
                bool lt_prev = (j > 0) &&
                    ((key < dk[j - 1]) || (key == dk[j - 1] && idx < ik[j - 1]));
                bool lt_here = (key < dk[j]) || (key == dk[j] && idx < ik[j]);
                if (lt_prev)      { dk[j] = dk[j - 1]; ik[j] = ik[j - 1]; }
                else if (lt_here) { dk[j] = key;       ik[j] = idx;       }
            }
        }
    }

#pragma unroll
    for (int j = 0; j < KK; ++j) {
        outD[(size_t)gq * KK + j] = sqrtf(dk[j]);
        outI[(size_t)gq * KK + j] = (float)ik[j];
    }
}

// ---------------------------------------------------------------------------
// Launch: ref = d_in[0], query = d_in[1].
// d_out layout: D [NB*NQ*KK] f32, then I [NB*NQ*KK] f32 (single output dtype).
// 6-launch sequence puts knn_mma at position 4 (launch #16 ≡ 4 mod 6) so the
// ncu sampler finally profiles it.
// ---------------------------------------------------------------------------
extern "C" void kernel_launch(void* const* d_in, const int* in_sizes, int n_in,
                              void* d_out, int out_size) {
    const float* ref   = (const float*)d_in[0];
    const float* query = (const float*)d_in[1];

    float* outD = (float*)d_out;
    float* outI = (float*)d_out + (size_t)NB * NQ * KK;

    cudaFuncSetAttribute(knn_mma, cudaFuncAttributeMaxDynamicSharedMemorySize, SMEM_BYTES);

    r2_kernel<<<(NB * NR + 255) / 256, 256>>>(ref);                       // 1
    cvt_kernel<<<(NB * NR * DIM / 2 + 255) / 256, 256>>>(ref);            // 2
    nop_kernel<<<1, 32>>>();                                              // 3
    knn_mma<<<dim3(NQ / QPB, NSPLIT, NB), QPB, SMEM_BYTES>>>(query);      // 4 <- profiled
    knn_rerank<<<(NB * NQ + 63) / 64, 64>>>(ref, query, outD, outI);      // 5
    nop_kernel<<<1, 32>>>();                                              // 6
}

// round 14
// speedup vs baseline: 2.0144x; 1.2389x over previous
#include <cuda_runtime.h>
#include <cuda_bf16.h>
#include <math_constants.h>
#include <mma.h>

using namespace nvcuda;

// Problem shape (fixed by the dataset)
#define NB 4
#define NQ 2048
#define NR 16384
#define DIM 64
#define KK 16
#define KC 20                   // candidates kept per split (margin over KK)
#define NSPLIT 4
#define QPB 128                 // queries per block
#define TRR 64                  // refs per tile
#define RPS (NR / NSPLIT)       // 4096 refs per split
#define NTILE (RPS / TRR)       // 64 tiles per split
#define NCAND (NSPLIT * KC)     // 80 candidates per query

#define LDQR 80                 // padded bf16 rows (64 data + r2hi/lo + zeros)
#define LDSC 68                 // score row stride (floats): float4 conflict-free

// Dynamic smem layout (float units). Q tile (bf16) ALIASES score tile.
#define OFF_SCORE 0
#define SCORE_SZ  (QPB * LDSC)                      // 8704 floats
#define OFF_REF   SCORE_SZ                          // bf16 [2][TRR][LDQR]
#define REF_SZ    ((2 * TRR * LDQR) / 2)            // 5120 floats
#define OFF_VAL   (OFF_REF + REF_SZ)                // [KC][QPB]
#define OFF_IDX   (OFF_VAL + KC * QPB)              // u16 [KC][QPB]
#define SMEM_FLOATS (OFF_IDX + (KC * QPB) / 2)
#define SMEM_BYTES  (SMEM_FLOATS * 4)               // 70656 B

// Scratch (device globals: harness forbids cudaMalloc)
__device__ float          g_r2[NB * NR];
__device__ __nv_bfloat16  g_ref_bf16[(size_t)NB * NR * DIM];
__device__ int            g_cand[(size_t)NB * NQ * NCAND];
__device__ float          g_part_d[(size_t)NB * NQ * NSPLIT * KK];
__device__ int            g_part_i[(size_t)NB * NQ * NSPLIT * KK];

// cp.async helpers
__device__ __forceinline__ void cp16(unsigned int dst, const void* src) {
    asm volatile("cp.async.cg.shared.global [%0], [%1], 16;" :: "r"(dst), "l"(src));
}
__device__ __forceinline__ void cp_commit() { asm volatile("cp.async.commit_group;"); }
__device__ __forceinline__ void cp_wait0()  { asm volatile("cp.async.wait_group 0;" ::: "memory"); }

// ---------------------------------------------------------------------------
// XLA-GPU row-reduction emulation for sum(x*x) over 64 elements (verified
// bit-exact vs reference in R8): strided lane accum + shfl_down tree.
// ---------------------------------------------------------------------------
__device__ __forceinline__ float xla_row_sumsq(const float* __restrict__ x) {
    float a[32];
#pragma unroll
    for (int l = 0; l < 32; ++l)
        a[l] = __fadd_rn(__fmul_rn(x[l], x[l]),
                         __fmul_rn(x[l + 32], x[l + 32]));
#pragma unroll
    for (int off = 16; off >= 1; off >>= 1) {
#pragma unroll
        for (int l = 0; l < 16; ++l)
            if (l < off)
                a[l] = __fadd_rn(a[l], a[l + off]);
    }
    return a[0];
}

// ---------------------------------------------------------------------------
// Kernel 0a: ref squared norms (exact f32, pass-1 filter only).
// ---------------------------------------------------------------------------
__global__ void r2_kernel(const float* __restrict__ ref) {
    int i = blockIdx.x * blockDim.x + threadIdx.x;
    if (i >= NB * NR) return;
    const float4* p = reinterpret_cast<const float4*>(ref + (size_t)i * DIM);
    float s = 0.f;
#pragma unroll
    for (int j = 0; j < DIM / 4; ++j) {
        float4 v = p[j];
        s += v.x * v.x + v.y * v.y + v.z * v.z + v.w * v.w;
    }
    g_r2[i] = s;
}

// ---------------------------------------------------------------------------
// Kernel 0b: ref f32 -> bf16 (one-time).
// ---------------------------------------------------------------------------
__global__ void cvt_kernel(const float* __restrict__ ref) {
    int i = blockIdx.x * blockDim.x + threadIdx.x;          // bf16x2 pair index
    if (i >= NB * NR * DIM / 2) return;
    const float2 v = reinterpret_cast<const float2*>(ref)[i];
    reinterpret_cast<__nv_bfloat162*>(g_ref_bf16)[i] = __float22bfloat162_rn(v);
}

// Launch-slot spacer (keeps knn_mma on the ncu-profiled slot).
__global__ void nop_kernel() {}

// ---------------------------------------------------------------------------
// Kernel 1: bf16 tensor-core candidate generation. Grid (NQ/QPB, NSPLIT, NB),
// 128 threads (4 warps).
//  - A (= -2*query bf16, cols 64/65 = 1.0) fragments hoisted ONCE (5 k-steps).
//  - Ref tiles (bf16) double-buffered; cols 64/65 carry r2 split hi/lo so the
//    MMA accumulator directly yields s = r2 - 2*dot. Cols 66..79 zero.
//  - Score tile stored ROW-major per query (ld=68): scan is float4 + min4 +
//    threshold -> ~1.5 instr/ref. Inserts: verified smem max-replace top-KC.
// ---------------------------------------------------------------------------
__global__ __launch_bounds__(QPB)
void knn_mma(const float* __restrict__ query) {
    extern __shared__ float sm[];
    float*          s_score = sm + OFF_SCORE;                         // [QPB][LDSC]
    __nv_bfloat16*  s_q     = reinterpret_cast<__nv_bfloat16*>(sm);   // alias (prologue)
    __nv_bfloat16*  s_ref   = reinterpret_cast<__nv_bfloat16*>(sm + OFF_REF); // [2][TRR][LDQR]
    float*          s_val   = sm + OFF_VAL;                           // [KC][QPB]
    unsigned short* s_idx   = reinterpret_cast<unsigned short*>(sm + OFF_IDX);

    const int b     = blockIdx.z;
    const int split = blockIdx.y;
    const int qc    = blockIdx.x;
    const int tid   = threadIdx.x;
    const int wid   = tid >> 5;

    // --- Zero ref pad columns (66..79) of both buffers, once ---
    for (int j = tid; j < 2 * TRR * 14; j += QPB) {
        int row = j / 14, c = j % 14;
        s_ref[row * LDQR + 66 + c] = __float2bfloat16(0.f);
    }

    // --- Prologue: -2*q tile in bf16; cols 64/65 = 1.0; 66..79 = 0 ---
    const float* qbase = query + ((size_t)b * NQ + (size_t)qc * QPB) * DIM;
#pragma unroll
    for (int j = 0; j < DIM; ++j) {
        int idx = j * QPB + tid;
        int row = idx >> 6, col = idx & 63;
        s_q[row * LDQR + col] = __float2bfloat16(-2.f * qbase[idx]);
    }
    {
        // rows: each thread owns row tid (QPB==128 rows)
        s_q[tid * LDQR + 64] = __float2bfloat16(1.f);
        s_q[tid * LDQR + 65] = __float2bfloat16(1.f);
#pragma unroll
        for (int c = 66; c < LDQR; ++c) s_q[tid * LDQR + c] = __float2bfloat16(0.f);
    }

    // Init selection buffers.
#pragma unroll
    for (int j = 0; j < KC; ++j) { s_val[j * QPB + tid] = CUDART_INF_F; s_idx[j * QPB + tid] = 0; }
    float mval  = CUDART_INF_F;
    int   mslot = 0;

    const __nv_bfloat16* refb = g_ref_bf16 + (size_t)b * NR * DIM;
    const float*         r2b  = g_r2 + b * NR;
    const int            base0 = split * RPS;

    // Async-load tile 0 (cols 0..63) + r2 hi/lo into cols 64/65.
#pragma unroll
    for (int j = 0; j < 4; ++j) {
        int idx16 = j * QPB + tid;          // 16-byte chunk index (512 total)
        int row   = idx16 >> 3;
        int c     = idx16 & 7;
        cp16((unsigned int)__cvta_generic_to_shared(&s_ref[row * LDQR + c * 8]),
             refb + (size_t)base0 * DIM + idx16 * 8);
    }
    cp_commit();
    if (tid < TRR) {
        float r2v = r2b[base0 + tid];
        __nv_bfloat16 hi = __float2bfloat16(r2v);
        __nv_bfloat16 lo = __float2bfloat16(r2v - __bfloat162float(hi));
        __nv_bfloat162 hl; hl.x = hi; hl.y = lo;
        *reinterpret_cast<__nv_bfloat162*>(&s_ref[tid * LDQR + 64]) = hl;
    }
    __syncthreads();   // q tile visible

    // Persistent A fragments: 2 m-subtiles x 5 k-steps (k=4 is the r2 slice).
    wmma::fragment<wmma::matrix_a, 16, 16, 16, __nv_bfloat16, wmma::row_major> af[2][5];
#pragma unroll
    for (int mi = 0; mi < 2; ++mi)
#pragma unroll
        for (int k = 0; k < 5; ++k)
            wmma::load_matrix_sync(af[mi][k],
                s_q + (wid * 32 + mi * 16) * LDQR + k * 16, LDQR);
    cp_wait0();
    __syncthreads();   // frags built; q region (aliased by score) may be clobbered

    for (int t = 0; t < NTILE; ++t) {
        const int buf   = t & 1;
        const int rbase = base0 + t * TRR;

        // Prefetch next tile (overlaps MMA + scan).
        if (t + 1 < NTILE) {
            const int nb_   = (t + 1) & 1;
            const int nbase = base0 + (t + 1) * TRR;
#pragma unroll
            for (int j = 0; j < 4; ++j) {
                int idx16 = j * QPB + tid;
                int row   = idx16 >> 3;
                int c     = idx16 & 7;
                cp16((unsigned int)__cvta_generic_to_shared(
                         &s_ref[nb_ * TRR * LDQR + row * LDQR + c * 8]),
                     refb + (size_t)nbase * DIM + idx16 * 8);
            }
            cp_commit();
            if (tid < TRR) {
                float r2v = r2b[nbase + tid];
                __nv_bfloat16 hi = __float2bfloat16(r2v);
                __nv_bfloat16 lo = __float2bfloat16(r2v - __bfloat162float(hi));
                __nv_bfloat162 hl; hl.x = hi; hl.y = lo;
                *reinterpret_cast<__nv_bfloat162*>(&s_ref[nb_ * TRR * LDQR + tid * LDQR + 64]) = hl;
            }
        }

        // MMA: B loads only (A register-resident). 4 n-subtiles, 5 k-steps.
        {
            wmma::fragment<wmma::accumulator, 16, 16, 16, float> acc[2][4];
#pragma unroll
            for (int mi = 0; mi < 2; ++mi)
#pragma unroll
                for (int ni = 0; ni < 4; ++ni)
                    wmma::fill_fragment(acc[mi][ni], 0.f);

#pragma unroll
            for (int k = 0; k < 5; ++k) {
                wmma::fragment<wmma::matrix_b, 16, 16, 16, __nv_bfloat16, wmma::col_major> bf[4];
#pragma unroll
                for (int ni = 0; ni < 4; ++ni)
                    wmma::load_matrix_sync(bf[ni],
                        s_ref + buf * TRR * LDQR + (ni * 16) * LDQR + k * 16, LDQR);
#pragma unroll
                for (int mi = 0; mi < 2; ++mi)
#pragma unroll
                    for (int ni = 0; ni < 4; ++ni)
                        wmma::mma_sync(acc[mi][ni], af[mi][k], bf[ni], acc[mi][ni]);
            }
            // ROW-major store: s_score[query][ref], ld = LDSC.
#pragma unroll
            for (int mi = 0; mi < 2; ++mi)
#pragma unroll
                for (int ni = 0; ni < 4; ++ni)
                    wmma::store_matrix_sync(s_score + (wid * 32 + mi * 16) * LDSC + ni * 16,
                                            acc[mi][ni], LDSC, wmma::mem_row_major);
        }
        __syncthreads();

        // Scan: thread tid reads its own contiguous row; s already = r2-2dot.
        {
            const float4* sp = reinterpret_cast<const float4*>(s_score + tid * LDSC);
#pragma unroll 4
            for (int r4 = 0; r4 < TRR / 4; ++r4) {
                float4 v = sp[r4];
                float mn = fminf(fminf(v.x, v.y), fminf(v.z, v.w));
                if (mn < mval) {
                    float ss[4] = {v.x, v.y, v.z, v.w};
#pragma unroll
                    for (int e = 0; e < 4; ++e) {
                        float s = ss[e];
                        if (s < mval) {
                            s_val[mslot * QPB + tid] = s;
                            s_idx[mslot * QPB + tid] = (unsigned short)(rbase + r4 * 4 + e);
                            float nm = -CUDART_INF_F; int ns = 0;
#pragma unroll
                            for (int j = 0; j < KC; ++j) {
                                float vv = s_val[j * QPB + tid];
                                if (vv > nm) { nm = vv; ns = j; }
                            }
                            mval = nm; mslot = ns;
                        }
                    }
                }
            }
        }

        cp_wait0();
        __syncthreads();
    }

    const int q = qc * QPB + tid;
    const size_t o = (((size_t)b * NQ + q) * NSPLIT + split) * KC;
#pragma unroll
    for (int j = 0; j < KC; ++j) g_cand[o + j] = (int)s_idx[j * QPB + tid];
}

// ---------------------------------------------------------------------------
// Kernel 2a: per-split exact rerank. One thread per (query, split); emulates
// the reference bit-exactly (VERIFIED R8):
//   dot   = single sequential fused-FMA chain, k ascending
//   r2,q2 = XLA warp row-reduction (strided lane accum + shfl tree)
//   key   = max( fl( fl(q2+r2) - fl(2*dot) ), 0 )
// Sorted top-16 by lexicographic (key, idx) -> g_part_d / g_part_i.
// ---------------------------------------------------------------------------
__global__ void knn_rerank_part(const float* __restrict__ ref,
                                const float* __restrict__ query) {
    int gid = blockIdx.x * blockDim.x + threadIdx.x;
    if (gid >= NB * NQ * NSPLIT) return;
    const int sp = gid & (NSPLIT - 1);
    const int gq = gid >> 2;
    const int b  = gq / NQ;

    const float4* qp = reinterpret_cast<const float4*>(query + (size_t)gq * DIM);
    float qv[DIM];
#pragma unroll
    for (int j = 0; j < DIM / 4; ++j) {
        float4 v = qp[j];
        qv[4 * j + 0] = v.x; qv[4 * j + 1] = v.y;
        qv[4 * j + 2] = v.z; qv[4 * j + 3] = v.w;
    }
    const float q2f = xla_row_sumsq(qv);

    float dk[KK];
    int   ik[KK];
#pragma unroll
    for (int j = 0; j < KK; ++j) { dk[j] = CUDART_INF_F; ik[j] = 0x7FFFFFFF; }

    const int* cand = g_cand + ((size_t)gq * NSPLIT + sp) * KC;
    const float4* refb = reinterpret_cast<const float4*>(ref + (size_t)b * NR * DIM);

    for (int c = 0; c < KC; ++c) {
        const int idx = cand[c];
        const float4* rp = refb + (size_t)idx * (DIM / 4);
        float rv[DIM];
#pragma unroll
        for (int j = 0; j < DIM / 4; ++j) {
            float4 v = rp[j];
            rv[4 * j + 0] = v.x; rv[4 * j + 1] = v.y;
            rv[4 * j + 2] = v.z; rv[4 * j + 3] = v.w;
        }
        float dotf = 0.f;
#pragma unroll
        for (int k = 0; k < DIM; ++k)
            dotf = fmaf(qv[k], rv[k], dotf);
        const float r2f = xla_row_sumsq(rv);

        const float s12 = __fadd_rn(q2f, r2f);
        const float t2d = __fmul_rn(2.0f, dotf);
        const float key = fmaxf(__fadd_rn(s12, -t2d), 0.f);

        bool better_last = (key < dk[KK - 1]) ||
                           (key == dk[KK - 1] && idx < ik[KK - 1]);
        if (better_last) {
#pragma unroll
            for (int j = KK - 1; j >= 0; --j) {
                bool lt_prev = (j > 0) &&
                    ((key < dk[j - 1]) || (key == dk[j - 1] && idx < ik[j - 1]));
                bool lt_here = (key < dk[j]) || (key == dk[j] && idx < ik[j]);
                if (lt_prev)      { dk[j] = dk[j - 1]; ik[j] = ik[j - 1]; }
                else if (lt_here) { dk[j] = key;       ik[j] = idx;       }
            }
        }
    }

    const size_t o = ((size_t)gq * NSPLIT + sp) * KK;
#pragma unroll
    for (int j = 0; j < KK; ++j) { g_part_d[o + j] = dk[j]; g_part_i[o + j] = ik[j]; }
}

// ---------------------------------------------------------------------------
// Kernel 2b: exact 4-way merge of sorted (key,idx) lists. One thread/query.
// Splits are index-ascending, lists sorted by (key, idx); strict-< scan over
// split heads reproduces top_k's stable lowest-index-first tie-break.
// ---------------------------------------------------------------------------
__global__ void knn_merge(float* __restrict__ outD, float* __restrict__ outI) {
    int gq = blockIdx.x * blockDim.x + threadIdx.x;
    if (gq >= NB * NQ) return;

    const float* pd = g_part_d + (size_t)gq * NSPLIT * KK;
    const int*   pi = g_part_i + (size_t)gq * NSPLIT * KK;
    int p[NSPLIT] = {0, 0, 0, 0};

    for (int k = 0; k < KK; ++k) {
        float bk = CUDART_INF_F; int bi = 0x7FFFFFFF; int bs = 0;
#pragma unroll
        for (int s = 0; s < NSPLIT; ++s) {
            float v = pd[s * KK + p[s]];
            int   i = pi[s * KK + p[s]];
            if (v < bk || (v == bk && i < bi)) { bk = v; bi = i; bs = s; }
        }
        ++p[bs];
        outD[(size_t)gq * KK + k] = sqrtf(bk);
        outI[(size_t)gq * KK + k] = (float)bi;
    }
}

// ---------------------------------------------------------------------------
// Launch: ref = d_in[0], query = d_in[1].
// d_out layout: D [NB*NQ*KK] f32, then I [NB*NQ*KK] f32 (single output dtype).
// 6-launch sequence keeps knn_mma on the ncu-profiled slot (#16 mod 6 == 4).
// ---------------------------------------------------------------------------
extern "C" void kernel_launch(void* const* d_in, const int* in_sizes, int n_in,
                              void* d_out, int out_size) {
    const float* ref   = (const float*)d_in[0];
    const float* query = (const float*)d_in[1];

    float* outD = (float*)d_out;
    float* outI = (float*)d_out + (size_t)NB * NQ * KK;

    cudaFuncSetAttribute(knn_mma, cudaFuncAttributeMaxDynamicSharedMemorySize, SMEM_BYTES);

    r2_kernel<<<(NB * NR + 255) / 256, 256>>>(ref);                        // 1
    cvt_kernel<<<(NB * NR * DIM / 2 + 255) / 256, 256>>>(ref);             // 2
    nop_kernel<<<1, 32>>>();                                               // 3
    knn_mma<<<dim3(NQ / QPB, NSPLIT, NB), QPB, SMEM_BYTES>>>(query);       // 4 <- profiled
    knn_rerank_part<<<(NB * NQ * NSPLIT + 127) / 128, 128>>>(ref, query);  // 5
    knn_merge<<<(NB * NQ + 127) / 128, 128>>>(outD, outI);                 // 6
}